// round 5
// baseline (speedup 1.0000x reference)
#include <cuda_runtime.h>
#include <math_constants.h>

#define ROWS_TOTAL 16384
#define DIM 1024
#define CDIM 256
#define NCODES 8192
#define RPB 32            // rows per argmin block
#define CPT 16            // codes per tile
#define NT (NCODES / CPT) // 512 tiles

typedef unsigned long long u64;

__device__ float g_h[ROWS_TOTAL * CDIM];   // normalized projections (16 MB scratch)
__device__ float g_hcsq[NCODES];           // 0.5 * ||c||^2 per code

__device__ __forceinline__ float lo2(u64 v) { return __uint_as_float((unsigned)v); }
__device__ __forceinline__ float hi2(u64 v) { return __uint_as_float((unsigned)(v >> 32)); }
__device__ __forceinline__ u64 pack2(float l, float h) {
    return ((u64)__float_as_uint(h) << 32) | (u64)__float_as_uint(l);
}
__device__ __forceinline__ u64 splat2(float v) {
    unsigned u = __float_as_uint(v); return ((u64)u << 32) | (u64)u;
}
__device__ __forceinline__ void fma2(u64& d, u64 a, u64 b) {
    asm("fma.rn.f32x2 %0, %1, %2, %0;" : "+l"(d) : "l"(a), "l"(b));
}
__device__ __forceinline__ void cp16(void* sdst, const void* gsrc) {
    unsigned s = (unsigned)__cvta_generic_to_shared(sdst);
    asm volatile("cp.async.cg.shared.global [%0], [%1], 16;\n" :: "r"(s), "l"(gsrc) : "memory");
}

// ---------------------------------------------------------------------------
// Kernel 1: 0.5 * ||c||^2 per codebook row. One warp per code.
// ---------------------------------------------------------------------------
__global__ void __launch_bounds__(256) csq_kernel(const float* __restrict__ cb) {
    int warp = threadIdx.x >> 5, lane = threadIdx.x & 31;
    int row = blockIdx.x * 8 + warp;
    const float* p = cb + (size_t)row * CDIM;
    float s = 0.f;
#pragma unroll
    for (int j = 0; j < 8; ++j) { float v = p[lane + 32 * j]; s = fmaf(v, v, s); }
#pragma unroll
    for (int o = 16; o; o >>= 1) s += __shfl_xor_sync(0xffffffffu, s, o);
    if (lane == 0) g_hcsq[row] = 0.5f * s;
}

// ---------------------------------------------------------------------------
// Kernel 2: h = LayerNorm(x @ W^T) -> g_h. 64 rows x 256 cols per block.
// Static smem 41,344 B (< 48KB, no opt-in). Thread (tx=tid&31, wy=tid>>5):
// rows wy*8+ii, cols 2*tx+64*jj (f32x2 packed).
// ---------------------------------------------------------------------------
__global__ void __launch_bounds__(256) gemm1_ln_kernel(const float* __restrict__ x,
                                                       const float* __restrict__ W) {
    __shared__ float As[32 * 65];    // [k][row]
    __shared__ float Bs[32 * 258];   // [k][col]
    int tid = threadIdx.x;
    int row0 = blockIdx.x * 64;
    int tx = tid & 31, wy = tid >> 5;

    u64 acc[8][4];
#pragma unroll
    for (int ii = 0; ii < 8; ++ii)
#pragma unroll
        for (int jj = 0; jj < 4; ++jj) acc[ii][jj] = 0ull;

    for (int k0 = 0; k0 < DIM; k0 += 32) {
        // x tile: 64 rows x 32 k, transpose to k-major
#pragma unroll
        for (int p = 0; p < 2; ++p) {
            int i = tid + p * 256;
            int r = i & 63, k4 = i >> 6;
            float4 v = *(const float4*)(x + (size_t)(row0 + r) * DIM + k0 + k4 * 4);
            As[(k4 * 4 + 0) * 65 + r] = v.x; As[(k4 * 4 + 1) * 65 + r] = v.y;
            As[(k4 * 4 + 2) * 65 + r] = v.z; As[(k4 * 4 + 3) * 65 + r] = v.w;
        }
        // W tile: 256 cols x 32 k, transpose to k-major
        {
            int k4 = tid & 7, cb_ = tid >> 3;
#pragma unroll
            for (int p = 0; p < 8; ++p) {
                int c = cb_ + p * 32;
                float4 v = *(const float4*)(W + (size_t)c * DIM + k0 + k4 * 4);
                Bs[(k4 * 4 + 0) * 258 + c] = v.x; Bs[(k4 * 4 + 1) * 258 + c] = v.y;
                Bs[(k4 * 4 + 2) * 258 + c] = v.z; Bs[(k4 * 4 + 3) * 258 + c] = v.w;
            }
        }
        __syncthreads();
#pragma unroll
        for (int kk = 0; kk < 32; ++kk) {
            u64 a2[8], b2[4];
#pragma unroll
            for (int ii = 0; ii < 8; ++ii) a2[ii] = splat2(As[kk * 65 + wy * 8 + ii]);
#pragma unroll
            for (int jj = 0; jj < 4; ++jj) b2[jj] = *(const u64*)(Bs + kk * 258 + 2 * tx + 64 * jj);
#pragma unroll
            for (int ii = 0; ii < 8; ++ii)
#pragma unroll
                for (int jj = 0; jj < 4; ++jj) fma2(acc[ii][jj], a2[ii], b2[jj]);
        }
        __syncthreads();
    }

    // LayerNorm per row (row spans the 32 lanes of one warp)
#pragma unroll
    for (int ii = 0; ii < 8; ++ii) {
        float s = 0.f, q = 0.f;
#pragma unroll
        for (int jj = 0; jj < 4; ++jj) {
            float lo = lo2(acc[ii][jj]), hi = hi2(acc[ii][jj]);
            s += lo + hi;
            q = fmaf(lo, lo, q); q = fmaf(hi, hi, q);
        }
#pragma unroll
        for (int o = 16; o; o >>= 1) {
            s += __shfl_xor_sync(0xffffffffu, s, o);
            q += __shfl_xor_sync(0xffffffffu, q, o);
        }
        float mean = s * (1.f / CDIM);
        float var  = q * (1.f / CDIM) - mean * mean;
        float rstd = rsqrtf(var + 1e-5f);
        int row = row0 + wy * 8 + ii;
#pragma unroll
        for (int jj = 0; jj < 4; ++jj) {
            float lo = (lo2(acc[ii][jj]) - mean) * rstd;
            float hi = (hi2(acc[ii][jj]) - mean) * rstd;
            *(u64*)(g_h + (size_t)row * CDIM + 2 * tx + 64 * jj) = pack2(lo, hi);
        }
    }
}

// ---------------------------------------------------------------------------
// Kernel 3: codes = argmin_k (0.5||c_k||^2 - h.c_k), written as FLOAT32
// (harness output dtype is float32; codes 0..8191 are exactly representable).
// 256 threads, 32 rows/block, 48KB dynamic smem exactly (no opt-in).
// Next codebook tile register-staged via LDG; tile stored with per-code
// 4-float rotation for conflict-free LDS.128.
// Thread (tx=tid&15 -> code tx, ty=tid>>4 -> rows 2ty, 2ty+1).
// ---------------------------------------------------------------------------
__global__ void __launch_bounds__(256) argmin_kernel(const float* __restrict__ cb,
                                                     float* __restrict__ out) {
    extern __shared__ float smem[];
    float* h_s = smem;              // 32*256
    float* cbt = smem + RPB * CDIM; // 16*256 (swizzled); overlaid by red_* after loop
    float* red_d = cbt;             // 32*16
    int*   red_i = (int*)(cbt + 512);

    int tid  = threadIdx.x;
    int row0 = blockIdx.x * RPB;

    // h tile: 8192 contiguous floats
    for (int i = tid; i < RPB * CDIM / 4; i += 256)
        cp16(h_s + i * 4, g_h + (size_t)row0 * CDIM + i * 4);
    // codebook tile 0 (swizzled: code c, float-k -> c*256 + ((k + 4c) & 255))
    for (int i = tid; i < CPT * CDIM / 4; i += 256) {
        int o = i * 4, c = o >> 8, k = o & 255;
        cp16(cbt + c * CDIM + ((k + 4 * c) & 255), cb + o);
    }
    asm volatile("cp.async.commit_group;\n" ::: "memory");
    asm volatile("cp.async.wait_group 0;\n" ::: "memory");
    __syncthreads();

    int tx = tid & 15, ty = tid >> 4;
    const float* a0p = h_s + (2 * ty + 0) * CDIM;
    const float* a1p = h_s + (2 * ty + 1) * CDIM;
    const float* bp  = cbt + tx * CDIM;
    int rot = (4 * tx) & 255;  // this thread's code-row rotation

    float best0 = CUDART_INF_F, best1 = CUDART_INF_F;
    int   bidx0 = 0, bidx1 = 0;

    for (int t = 0; t < NT; ++t) {
        // stage tile t+1 into registers (consumed ~900 cycles later)
        float4 stg[4];
        if (t + 1 < NT) {
            const float* src = cb + (size_t)(t + 1) * CPT * CDIM;
#pragma unroll
            for (int j = 0; j < 4; ++j)
                stg[j] = __ldg((const float4*)(src + (tid + 256 * j) * 4));
        }

        u64 acc0 = 0ull, acc1 = 0ull;
#pragma unroll 8
        for (int k = 0; k < CDIM; k += 4) {
            float4 b  = *(const float4*)(bp + ((k + rot) & 255));
            float4 a0 = *(const float4*)(a0p + k);
            float4 a1 = *(const float4*)(a1p + k);
            u64 blo = pack2(b.x, b.y), bhi = pack2(b.z, b.w);
            fma2(acc0, pack2(a0.x, a0.y), blo);
            fma2(acc0, pack2(a0.z, a0.w), bhi);
            fma2(acc1, pack2(a1.x, a1.y), blo);
            fma2(acc1, pack2(a1.z, a1.w), bhi);
        }
        float q = __ldg(g_hcsq + t * CPT + tx);   // 0.5*||c||^2
        float d0 = q - (lo2(acc0) + hi2(acc0));
        float d1 = q - (lo2(acc1) + hi2(acc1));
        int cidx = t * CPT + tx;
        if (d0 < best0) { best0 = d0; bidx0 = cidx; }   // strict <: first-min ties
        if (d1 < best1) { best1 = d1; bidx1 = cidx; }

        __syncthreads();   // all threads done reading cbt
        if (t + 1 < NT) {
#pragma unroll
            for (int j = 0; j < 4; ++j) {
                int o = (tid + 256 * j) * 4, c = o >> 8, k = o & 255;
                *(float4*)(cbt + c * CDIM + ((k + 4 * c) & 255)) = stg[j];
            }
        }
        __syncthreads();   // tile t+1 visible to all
    }

    // cross-thread reduction: 16 candidates per row, lexicographic (dist, idx)
    red_d[(2 * ty + 0) * 16 + tx] = best0;  red_i[(2 * ty + 0) * 16 + tx] = bidx0;
    red_d[(2 * ty + 1) * 16 + tx] = best1;  red_i[(2 * ty + 1) * 16 + tx] = bidx1;
    __syncthreads();
    if (tid < RPB) {
        float bd = red_d[tid * 16]; int bi = red_i[tid * 16];
#pragma unroll
        for (int j = 1; j < 16; ++j) {
            float d = red_d[tid * 16 + j]; int i2 = red_i[tid * 16 + j];
            if (d < bd || (d == bd && i2 < bi)) { bd = d; bi = i2; }
        }
        out[row0 + tid] = (float)bi;   // FLOAT output: harness __output__ dtype
    }
}

// ---------------------------------------------------------------------------
extern "C" void kernel_launch(void* const* d_in, const int* in_sizes, int n_in,
                              void* d_out, int out_size) {
    // Identify inputs by element count (robust to ordering):
    //   x: 16,777,216 ; W: 262,144 ; codebook: 2,097,152
    const float *x = 0, *W = 0, *cbk = 0;
    for (int i = 0; i < n_in; ++i) {
        if      (in_sizes[i] == ROWS_TOTAL * DIM) x   = (const float*)d_in[i];
        else if (in_sizes[i] == CDIM * DIM)       W   = (const float*)d_in[i];
        else if (in_sizes[i] == NCODES * CDIM)    cbk = (const float*)d_in[i];
    }
    float* out = (float*)d_out;
    if (!x || !W || !cbk) return;

    csq_kernel<<<NCODES / 8, 256>>>(cbk);
    gemm1_ln_kernel<<<ROWS_TOTAL / 64, 256>>>(x, W);
    // 49,152 B dynamic smem: within the default 48KB cap, no opt-in required.
    argmin_kernel<<<ROWS_TOTAL / RPB, 256, (RPB + CPT) * CDIM * 4>>>(cbk, out);
}

// round 6
// speedup vs baseline: 4.4676x; 4.4676x over previous
#include <cuda_runtime.h>
#include <math_constants.h>

#define ROWS_TOTAL 16384
#define DIM 1024
#define CDIM 256
#define NCODES 8192
#define CBP 260             // smem pitch (floats) for h and cb-chunk tiles

typedef unsigned long long u64;

__device__ float g_h[ROWS_TOTAL * CDIM];     // normalized projections (16 MB)
__device__ float g_cbT[CDIM * NCODES];       // transposed codebook [k][code] (8 MB)
__device__ float g_hcsq[NCODES];             // 0.5 * ||c||^2

__device__ __forceinline__ float lo2(u64 v) { return __uint_as_float((unsigned)v); }
__device__ __forceinline__ float hi2(u64 v) { return __uint_as_float((unsigned)(v >> 32)); }
__device__ __forceinline__ u64 pack2(float l, float h) {
    return ((u64)__float_as_uint(h) << 32) | (u64)__float_as_uint(l);
}
__device__ __forceinline__ u64 splat2(float v) {
    unsigned u = __float_as_uint(v); return ((u64)u << 32) | (u64)u;
}
__device__ __forceinline__ void fma2(u64& d, u64 a, u64 b) {
    asm("fma.rn.f32x2 %0, %1, %2, %0;" : "+l"(d) : "l"(a), "l"(b));
}
__device__ __forceinline__ void cp16(void* sdst, const void* gsrc) {
    unsigned s = (unsigned)__cvta_generic_to_shared(sdst);
    asm volatile("cp.async.cg.shared.global [%0], [%1], 16;\n" :: "r"(s), "l"(gsrc) : "memory");
}
#define CP_COMMIT() asm volatile("cp.async.commit_group;\n" ::: "memory")
#define CP_WAIT0()  asm volatile("cp.async.wait_group 0;\n" ::: "memory")

// ---------------------------------------------------------------------------
// Kernel 1: 0.5*||c||^2 per code. One warp per code row.
// ---------------------------------------------------------------------------
__global__ void __launch_bounds__(256) csq_kernel(const float* __restrict__ cb) {
    int warp = threadIdx.x >> 5, lane = threadIdx.x & 31;
    int row = blockIdx.x * 8 + warp;
    const float* p = cb + (size_t)row * CDIM;
    float s = 0.f;
#pragma unroll
    for (int j = 0; j < 8; ++j) { float v = p[lane + 32 * j]; s = fmaf(v, v, s); }
#pragma unroll
    for (int o = 16; o; o >>= 1) s += __shfl_xor_sync(0xffffffffu, s, o);
    if (lane == 0) g_hcsq[row] = 0.5f * s;
}

// ---------------------------------------------------------------------------
// Kernel 1b: transpose codebook [8192 codes][256 k] -> g_cbT [256 k][8192].
// ---------------------------------------------------------------------------
__global__ void __launch_bounds__(256) transpose_cb_kernel(const float* __restrict__ cb) {
    __shared__ float t[32][33];
    int tx = threadIdx.x & 31, ty = threadIdx.x >> 5;   // ty 0..7
    int c0 = blockIdx.x * 32, k0 = blockIdx.y * 32;
#pragma unroll
    for (int j = 0; j < 32; j += 8)
        t[ty + j][tx] = cb[(size_t)(c0 + ty + j) * CDIM + k0 + tx];
    __syncthreads();
#pragma unroll
    for (int j = 0; j < 32; j += 8)
        g_cbT[(size_t)(k0 + ty + j) * NCODES + c0 + tx] = t[tx][ty + j];
}

// ---------------------------------------------------------------------------
// Kernel 2: h = LayerNorm(x @ W^T) -> g_h (row-major). Unchanged from R5.
// ---------------------------------------------------------------------------
__global__ void __launch_bounds__(256) gemm1_ln_kernel(const float* __restrict__ x,
                                                       const float* __restrict__ W) {
    __shared__ float As[32 * 65];
    __shared__ float Bs[32 * 258];
    int tid = threadIdx.x;
    int row0 = blockIdx.x * 64;
    int tx = tid & 31, wy = tid >> 5;

    u64 acc[8][4];
#pragma unroll
    for (int ii = 0; ii < 8; ++ii)
#pragma unroll
        for (int jj = 0; jj < 4; ++jj) acc[ii][jj] = 0ull;

    for (int k0 = 0; k0 < DIM; k0 += 32) {
#pragma unroll
        for (int p = 0; p < 2; ++p) {
            int i = tid + p * 256;
            int r = i & 63, k4 = i >> 6;
            float4 v = *(const float4*)(x + (size_t)(row0 + r) * DIM + k0 + k4 * 4);
            As[(k4 * 4 + 0) * 65 + r] = v.x; As[(k4 * 4 + 1) * 65 + r] = v.y;
            As[(k4 * 4 + 2) * 65 + r] = v.z; As[(k4 * 4 + 3) * 65 + r] = v.w;
        }
        {
            int k4 = tid & 7, cb_ = tid >> 3;
#pragma unroll
            for (int p = 0; p < 8; ++p) {
                int c = cb_ + p * 32;
                float4 v = *(const float4*)(W + (size_t)c * DIM + k0 + k4 * 4);
                Bs[(k4 * 4 + 0) * 258 + c] = v.x; Bs[(k4 * 4 + 1) * 258 + c] = v.y;
                Bs[(k4 * 4 + 2) * 258 + c] = v.z; Bs[(k4 * 4 + 3) * 258 + c] = v.w;
            }
        }
        __syncthreads();
#pragma unroll
        for (int kk = 0; kk < 32; ++kk) {
            u64 a2[8], b2[4];
#pragma unroll
            for (int ii = 0; ii < 8; ++ii) a2[ii] = splat2(As[kk * 65 + wy * 8 + ii]);
#pragma unroll
            for (int jj = 0; jj < 4; ++jj) b2[jj] = *(const u64*)(Bs + kk * 258 + 2 * tx + 64 * jj);
#pragma unroll
            for (int ii = 0; ii < 8; ++ii)
#pragma unroll
                for (int jj = 0; jj < 4; ++jj) fma2(acc[ii][jj], a2[ii], b2[jj]);
        }
        __syncthreads();
    }

#pragma unroll
    for (int ii = 0; ii < 8; ++ii) {
        float s = 0.f, q = 0.f;
#pragma unroll
        for (int jj = 0; jj < 4; ++jj) {
            float lo = lo2(acc[ii][jj]), hi = hi2(acc[ii][jj]);
            s += lo + hi;
            q = fmaf(lo, lo, q); q = fmaf(hi, hi, q);
        }
#pragma unroll
        for (int o = 16; o; o >>= 1) {
            s += __shfl_xor_sync(0xffffffffu, s, o);
            q += __shfl_xor_sync(0xffffffffu, q, o);
        }
        float mean = s * (1.f / CDIM);
        float var  = q * (1.f / CDIM) - mean * mean;
        float rstd = rsqrtf(var + 1e-5f);
        int row = row0 + wy * 8 + ii;
#pragma unroll
        for (int jj = 0; jj < 4; ++jj) {
            float lo = (lo2(acc[ii][jj]) - mean) * rstd;
            float hi = (hi2(acc[ii][jj]) - mean) * rstd;
            *(u64*)(g_h + (size_t)row * CDIM + 2 * tx + 64 * jj) = pack2(lo, hi);
        }
    }
}

// ---------------------------------------------------------------------------
// Kernel 3 v2: argmin over codes of (0.5||c||^2 - h.c), float32 output.
// Block: 256 threads, 64 rows x ALL 8192 codes.
//   - h tile (64 x 256, row-major, pitch 260) resident in smem.
//   - codebook streamed k-major from g_cbT in 256 chunks (32 k x 256 codes),
//     double-buffered cp.async.
//   - thread (tx=tid&31, wy=tid>>5): rows wy*8+ii, codes 2*tx+64*jj(+e).
//     Per kk: 8 uniform-broadcast A scalars + 4 LDS.64 B => 32 FMA2.
// Smem: 135,168 B (opt-in), 1 block/SM.
// ---------------------------------------------------------------------------
__global__ void __launch_bounds__(256) argmin_kernel(float* __restrict__ out) {
    extern __shared__ float smem[];
    float* h_s  = smem;                      // 64*260 = 16640
    float* cbuf0 = smem + 16640;             // 32*260 = 8320
    float* cbuf1 = smem + 24960;             // 32*260
    float* qsb  = smem + 33280;              // 2*256
    float* red_d = cbuf0;                    // overlay after main loop
    int*   red_i = (int*)(cbuf0 + 2048);

    int tid  = threadIdx.x;
    int row0 = blockIdx.x * 64;
    int tx = tid & 31, wy = tid >> 5;

    // Initial loads: h tile + chunk 0 + qs(ct=0), one group.
    for (int i = tid; i < 64 * 64; i += 256) {
        int r = i >> 6, j = i & 63;
        cp16(h_s + r * CBP + j * 4, g_h + (size_t)(row0 + r) * CDIM + j * 4);
    }
    for (int i = tid; i < 32 * 64; i += 256) {
        int kk = i >> 6, j = i & 63;
        cp16(cbuf0 + kk * CBP + j * 4, g_cbT + (size_t)kk * NCODES + j * 4);
    }
    if (tid < 64) cp16(qsb + tid * 4, g_hcsq + tid * 4);
    CP_COMMIT();

    u64 acc[8][4];
    float best[8]; int bidx[8];
#pragma unroll
    for (int ii = 0; ii < 8; ++ii) { best[ii] = CUDART_INF_F; bidx[ii] = 0; }

    for (int c = 0; c < 256; ++c) {          // 32 code-tiles x 8 k-chunks
        int ct = c >> 3, kc = c & 7;
        CP_WAIT0();
        __syncthreads();                      // chunk c resident; all warps past chunk c-1

        if (c + 1 < 256) {                    // prefetch chunk c+1
            int ct2 = (c + 1) >> 3, kc2 = (c + 1) & 7;
            float* nb = ((c + 1) & 1) ? cbuf1 : cbuf0;
            const float* src = g_cbT + (size_t)(kc2 * 32) * NCODES + ct2 * 256;
            for (int i = tid; i < 32 * 64; i += 256) {
                int kk = i >> 6, j = i & 63;
                cp16(nb + kk * CBP + j * 4, src + (size_t)kk * NCODES + j * 4);
            }
            if (kc2 == 0 && tid < 64)
                cp16(qsb + ((ct2 & 1) << 8) + tid * 4, g_hcsq + ct2 * 256 + tid * 4);
            CP_COMMIT();
        }

        const float* Bs = (c & 1) ? cbuf1 : cbuf0;
        const float* Ap = h_s + wy * 8 * CBP + kc * 32;

        if (kc == 0) {
#pragma unroll
            for (int ii = 0; ii < 8; ++ii)
#pragma unroll
                for (int jj = 0; jj < 4; ++jj) acc[ii][jj] = 0ull;
        }
#pragma unroll 8
        for (int kk = 0; kk < 32; ++kk) {
            u64 b2[4];
#pragma unroll
            for (int jj = 0; jj < 4; ++jj)
                b2[jj] = *(const u64*)(Bs + kk * CBP + 2 * tx + 64 * jj);
#pragma unroll
            for (int ii = 0; ii < 8; ++ii) {
                u64 a2 = splat2(Ap[ii * CBP + kk]);
#pragma unroll
                for (int jj = 0; jj < 4; ++jj) fma2(acc[ii][jj], a2, b2[jj]);
            }
        }

        if (kc == 7) {                        // argmin update for this code tile
            const float* qp = qsb + ((ct & 1) << 8);
            int cb0_ = ct * 256;
#pragma unroll
            for (int jj = 0; jj < 4; ++jj) {  // ascending code order within thread
                u64 qq = *(const u64*)(qp + 2 * tx + 64 * jj);
                float ql = lo2(qq), qh = hi2(qq);
                int ce = cb0_ + 2 * tx + 64 * jj;
#pragma unroll
                for (int ii = 0; ii < 8; ++ii) {
                    float d0 = ql - lo2(acc[ii][jj]);
                    float d1 = qh - hi2(acc[ii][jj]);
                    if (d0 < best[ii]) { best[ii] = d0; bidx[ii] = ce; }
                    if (d1 < best[ii]) { best[ii] = d1; bidx[ii] = ce + 1; }
                }
            }
        }
    }

    // Cross-thread reduce: 32 candidates per row, lexicographic (dist, idx).
    __syncthreads();
#pragma unroll
    for (int ii = 0; ii < 8; ++ii) {
        int row = wy * 8 + ii;
        red_d[row * 32 + tx] = best[ii];
        red_i[row * 32 + tx] = bidx[ii];
    }
    __syncthreads();
    if (tid < 64) {
        float bd = red_d[tid * 32]; int bi = red_i[tid * 32];
#pragma unroll
        for (int j = 1; j < 32; ++j) {
            float d = red_d[tid * 32 + j]; int i2 = red_i[tid * 32 + j];
            if (d < bd || (d == bd && i2 < bi)) { bd = d; bi = i2; }
        }
        out[row0 + tid] = (float)bi;          // float32: harness __output__ dtype
    }
}

// ---------------------------------------------------------------------------
extern "C" void kernel_launch(void* const* d_in, const int* in_sizes, int n_in,
                              void* d_out, int out_size) {
    // Identify inputs by element count (robust to ordering).
    const float *x = 0, *W = 0, *cbk = 0;
    for (int i = 0; i < n_in; ++i) {
        if      (in_sizes[i] == ROWS_TOTAL * DIM) x   = (const float*)d_in[i];
        else if (in_sizes[i] == CDIM * DIM)       W   = (const float*)d_in[i];
        else if (in_sizes[i] == NCODES * CDIM)    cbk = (const float*)d_in[i];
    }
    float* out = (float*)d_out;
    if (!x || !W || !cbk) return;

    csq_kernel<<<NCODES / 8, 256>>>(cbk);
    {
        dim3 g(NCODES / 32, CDIM / 32);
        transpose_cb_kernel<<<g, 256>>>(cbk);
    }
    gemm1_ln_kernel<<<ROWS_TOTAL / 64, 256>>>(x, W);

    const int smem_bytes = (16640 + 2 * 8320 + 512) * 4;   // 135,168 B
    cudaFuncSetAttribute(argmin_kernel, cudaFuncAttributeMaxDynamicSharedMemorySize, smem_bytes);
    argmin_kernel<<<ROWS_TOTAL / 64, 256, smem_bytes>>>(out);
}

// round 8
// speedup vs baseline: 8.4947x; 1.9014x over previous
#include <cuda_runtime.h>
#include <cuda_bf16.h>
#include <math_constants.h>
#include <cstdint>

#define ROWS_TOTAL 16384
#define DIM 1024
#define CDIM 256
#define NCODES 8192

typedef unsigned long long u64;

__device__ float g_h[ROWS_TOTAL * CDIM];            // normalized projections (fp32, for rescore)
__device__ float g_hcsq[NCODES];                    // 0.5*||c||^2
__device__ __nv_bfloat16 g_hh[ROWS_TOTAL * CDIM];   // h bf16 hi
__device__ __nv_bfloat16 g_hl[ROWS_TOTAL * CDIM];   // h bf16 lo
__device__ __nv_bfloat16 g_cbh[NCODES * CDIM];      // codebook bf16 hi
__device__ __nv_bfloat16 g_cbl[NCODES * CDIM];      // codebook bf16 lo
__device__ int2 g_cand[ROWS_TOTAL];                 // top-2 candidates per row

// ---------------- helpers ----------------
__device__ __forceinline__ float lo2(u64 v) { return __uint_as_float((unsigned)v); }
__device__ __forceinline__ float hi2(u64 v) { return __uint_as_float((unsigned)(v >> 32)); }
__device__ __forceinline__ u64 pack2(float l, float h) {
    return ((u64)__float_as_uint(h) << 32) | (u64)__float_as_uint(l);
}
__device__ __forceinline__ u64 splat2(float v) {
    unsigned u = __float_as_uint(v); return ((u64)u << 32) | (u64)u;
}
__device__ __forceinline__ void fma2(u64& d, u64 a, u64 b) {
    asm("fma.rn.f32x2 %0, %1, %2, %0;" : "+l"(d) : "l"(a), "l"(b));
}
__device__ __forceinline__ void cp16(void* sdst, const void* gsrc) {
    unsigned s = (unsigned)__cvta_generic_to_shared(sdst);
    asm volatile("cp.async.cg.shared.global [%0], [%1], 16;\n" :: "r"(s), "l"(gsrc) : "memory");
}
#define CP_COMMIT() asm volatile("cp.async.commit_group;\n" ::: "memory")
#define CP_WAIT0()  asm volatile("cp.async.wait_group 0;\n" ::: "memory")

__device__ __forceinline__ uint32_t smem_u32(const void* p) {
    uint32_t a;
    asm("{ .reg .u64 t; cvta.to.shared.u64 t, %1; cvt.u32.u64 %0, t; }" : "=r"(a) : "l"(p));
    return a;
}
__device__ __forceinline__ void ldsm_x4(uint32_t* r, uint32_t addr) {
    asm volatile("ldmatrix.sync.aligned.m8n8.x4.shared.b16 {%0,%1,%2,%3}, [%4];"
                 : "=r"(r[0]), "=r"(r[1]), "=r"(r[2]), "=r"(r[3]) : "r"(addr));
}
__device__ __forceinline__ void ldsm_x2(uint32_t* r, uint32_t addr) {
    asm volatile("ldmatrix.sync.aligned.m8n8.x2.shared.b16 {%0,%1}, [%2];"
                 : "=r"(r[0]), "=r"(r[1]) : "r"(addr));
}
__device__ __forceinline__ void mma16816(float* d, const uint32_t* a, const uint32_t* b) {
    asm volatile("mma.sync.aligned.m16n8k16.row.col.f32.bf16.bf16.f32 "
                 "{%0,%1,%2,%3}, {%4,%5,%6,%7}, {%8,%9}, {%0,%1,%2,%3};"
                 : "+f"(d[0]), "+f"(d[1]), "+f"(d[2]), "+f"(d[3])
                 : "r"(a[0]), "r"(a[1]), "r"(a[2]), "r"(a[3]), "r"(b[0]), "r"(b[1]));
}

// smem layout (bytes): A[2 splits][64 rows][528B] | B[2 bufs][2 splits][64][528] | csq[2][64]f
#define PITCH    528
#define ASPLIT   33792
#define B_OFF    67584
#define BBUF     67584
#define BSPLIT   33792
#define CSQ_OFF  202752
#define SM_TOTAL 203264
#define RED_OFF  67584            // reduce overlay (on B buf 0, after main loop)

// ---------------------------------------------------------------------------
// Kernel 1: 0.5*||c||^2
// ---------------------------------------------------------------------------
__global__ void __launch_bounds__(256) csq_kernel(const float* __restrict__ cb) {
    int warp = threadIdx.x >> 5, lane = threadIdx.x & 31;
    int row = blockIdx.x * 8 + warp;
    const float* p = cb + (size_t)row * CDIM;
    float s = 0.f;
#pragma unroll
    for (int j = 0; j < 8; ++j) { float v = p[lane + 32 * j]; s = fmaf(v, v, s); }
#pragma unroll
    for (int o = 16; o; o >>= 1) s += __shfl_xor_sync(0xffffffffu, s, o);
    if (lane == 0) g_hcsq[row] = 0.5f * s;
}

// ---------------------------------------------------------------------------
// Kernel 1b: bf16 hi/lo split of codebook
// ---------------------------------------------------------------------------
__global__ void __launch_bounds__(256) cbsplit_kernel(const float* __restrict__ cb) {
    int i = (blockIdx.x * 256 + threadIdx.x) * 4;
#pragma unroll
    for (int j = 0; j < 4; ++j) {
        float v = cb[i + j];
        __nv_bfloat16 h = __float2bfloat16(v);
        g_cbh[i + j] = h;
        g_cbl[i + j] = __float2bfloat16(v - __bfloat162float(h));
    }
}

// ---------------------------------------------------------------------------
// Kernel 2: h = LayerNorm(x @ W^T) -> g_h (fp32) + g_hh/g_hl (bf16 hi/lo)
// ---------------------------------------------------------------------------
__global__ void __launch_bounds__(256) gemm1_ln_kernel(const float* __restrict__ x,
                                                       const float* __restrict__ W) {
    __shared__ float As[32 * 65];
    __shared__ float Bs[32 * 258];
    int tid = threadIdx.x;
    int row0 = blockIdx.x * 64;
    int tx = tid & 31, wy = tid >> 5;

    u64 acc[8][4];
#pragma unroll
    for (int ii = 0; ii < 8; ++ii)
#pragma unroll
        for (int jj = 0; jj < 4; ++jj) acc[ii][jj] = 0ull;

    for (int k0 = 0; k0 < DIM; k0 += 32) {
#pragma unroll
        for (int p = 0; p < 2; ++p) {
            int i = tid + p * 256;
            int r = i & 63, k4 = i >> 6;
            float4 v = *(const float4*)(x + (size_t)(row0 + r) * DIM + k0 + k4 * 4);
            As[(k4 * 4 + 0) * 65 + r] = v.x; As[(k4 * 4 + 1) * 65 + r] = v.y;
            As[(k4 * 4 + 2) * 65 + r] = v.z; As[(k4 * 4 + 3) * 65 + r] = v.w;
        }
        {
            int k4 = tid & 7, cb_ = tid >> 3;
#pragma unroll
            for (int p = 0; p < 8; ++p) {
                int c = cb_ + p * 32;
                float4 v = *(const float4*)(W + (size_t)c * DIM + k0 + k4 * 4);
                Bs[(k4 * 4 + 0) * 258 + c] = v.x; Bs[(k4 * 4 + 1) * 258 + c] = v.y;
                Bs[(k4 * 4 + 2) * 258 + c] = v.z; Bs[(k4 * 4 + 3) * 258 + c] = v.w;
            }
        }
        __syncthreads();
#pragma unroll
        for (int kk = 0; kk < 32; ++kk) {
            u64 a2[8], b2[4];
#pragma unroll
            for (int ii = 0; ii < 8; ++ii) a2[ii] = splat2(As[kk * 65 + wy * 8 + ii]);
#pragma unroll
            for (int jj = 0; jj < 4; ++jj) b2[jj] = *(const u64*)(Bs + kk * 258 + 2 * tx + 64 * jj);
#pragma unroll
            for (int ii = 0; ii < 8; ++ii)
#pragma unroll
                for (int jj = 0; jj < 4; ++jj) fma2(acc[ii][jj], a2[ii], b2[jj]);
        }
        __syncthreads();
    }

#pragma unroll
    for (int ii = 0; ii < 8; ++ii) {
        float s = 0.f, q = 0.f;
#pragma unroll
        for (int jj = 0; jj < 4; ++jj) {
            float lo = lo2(acc[ii][jj]), hi = hi2(acc[ii][jj]);
            s += lo + hi;
            q = fmaf(lo, lo, q); q = fmaf(hi, hi, q);
        }
#pragma unroll
        for (int o = 16; o; o >>= 1) {
            s += __shfl_xor_sync(0xffffffffu, s, o);
            q += __shfl_xor_sync(0xffffffffu, q, o);
        }
        float mean = s * (1.f / CDIM);
        float var  = q * (1.f / CDIM) - mean * mean;
        float rstd = rsqrtf(var + 1e-5f);
        size_t row = row0 + wy * 8 + ii;
#pragma unroll
        for (int jj = 0; jj < 4; ++jj) {
            float lo = (lo2(acc[ii][jj]) - mean) * rstd;
            float hi = (hi2(acc[ii][jj]) - mean) * rstd;
            size_t off = row * CDIM + 2 * tx + 64 * jj;
            *(u64*)(g_h + off) = pack2(lo, hi);
            __nv_bfloat16 h0 = __float2bfloat16(lo);
            __nv_bfloat16 h1 = __float2bfloat16(hi);
            __nv_bfloat16 l0 = __float2bfloat16(lo - __bfloat162float(h0));
            __nv_bfloat16 l1 = __float2bfloat16(hi - __bfloat162float(h1));
            *(uint32_t*)((unsigned short*)g_hh + off) =
                (uint32_t)__bfloat16_as_ushort(h0) | ((uint32_t)__bfloat16_as_ushort(h1) << 16);
            *(uint32_t*)((unsigned short*)g_hl + off) =
                (uint32_t)__bfloat16_as_ushort(l0) | ((uint32_t)__bfloat16_as_ushort(l1) << 16);
        }
    }
}

// ---------------------------------------------------------------------------
// Kernel 3: bf16x3 warp-MMA (m16n8k16) distance GEMM + per-row top-2.
// CTA = 64 rows x all codes (128 tiles of 64 codes, double-buffered).
// Warp (of 8): rows (warp&1)*32 + [0,32), codes (warp>>1)*16 + [0,16).
// dot = Ah*Bh + Al*Bh + Ah*Bl (fp32 acc); dist = 0.5||c||^2 - dot.
// ---------------------------------------------------------------------------
__global__ void __launch_bounds__(256, 1) mma_argmin_kernel() {
    extern __shared__ __align__(1024) char smem[];
    uint32_t sb = smem_u32(smem);
    float* csq_s = (float*)(smem + CSQ_OFF);
    int tid = threadIdx.x, lane = tid & 31, warp = tid >> 5;
    int row0 = blockIdx.x * 64;

    // preload: A tile (h bf16 hi/lo), B tile 0, csq slot 0
    for (int i = tid; i < 4096; i += 256) {
        int split = i >> 11, idx = i & 2047, r = idx >> 5, j = idx & 31;
        const __nv_bfloat16* src = (split ? g_hl : g_hh) + (size_t)(row0 + r) * CDIM + j * 8;
        cp16(smem + split * ASPLIT + r * PITCH + j * 16, src);
    }
    for (int i = tid; i < 4096; i += 256) {
        int split = i >> 11, idx = i & 2047, r = idx >> 5, j = idx & 31;
        const __nv_bfloat16* src = (split ? g_cbl : g_cbh) + (size_t)r * CDIM + j * 8;
        cp16(smem + B_OFF + split * BSPLIT + r * PITCH + j * 16, src);
    }
    if (tid < 16) cp16((char*)csq_s + tid * 16, g_hcsq + tid * 4);
    CP_COMMIT();

    int mrow0 = (warp & 1) * 32;        // row group within CTA
    int ncol0 = (warp >> 1) * 16;       // code group within a 64-code tile
    // ldmatrix lane addresses (A: x4, rows m; B: x2, rows n)
    uint32_t a_addr = sb + (uint32_t)(mrow0 + (lane & 7) + 8 * ((lane >> 3) & 1)) * PITCH
                         + (uint32_t)(lane >> 4) * 16;
    uint32_t b_addr = sb + B_OFF + (uint32_t)(ncol0 + (lane & 7)) * PITCH
                         + (uint32_t)((lane >> 3) & 1) * 16;

    float best1[4], best2[4]; int id1[4], id2[4];
#pragma unroll
    for (int s = 0; s < 4; ++s) { best1[s] = CUDART_INF_F; best2[s] = CUDART_INF_F; id1[s] = 0; id2[s] = 0; }

    for (int t = 0; t < 128; ++t) {
        CP_WAIT0();
        __syncthreads();                           // B[t&1] + csq[t&1] resident; buf (t+1)&1 free

        if (t + 1 < 128) {
            int c0 = (t + 1) * 64;
            char* buf = smem + B_OFF + ((t + 1) & 1) * BBUF;
            for (int i = tid; i < 4096; i += 256) {
                int split = i >> 11, idx = i & 2047, r = idx >> 5, j = idx & 31;
                const __nv_bfloat16* src = (split ? g_cbl : g_cbh) + (size_t)(c0 + r) * CDIM + j * 8;
                cp16(buf + split * BSPLIT + r * PITCH + j * 16, src);
            }
            if (tid < 16) cp16((char*)csq_s + ((t + 1) & 1) * 256 + tid * 16, g_hcsq + c0 + tid * 4);
            CP_COMMIT();
        }

        float acc[2][2][4];
#pragma unroll
        for (int mt = 0; mt < 2; ++mt)
#pragma unroll
            for (int nt = 0; nt < 2; ++nt)
#pragma unroll
                for (int r = 0; r < 4; ++r) acc[mt][nt][r] = 0.f;

        uint32_t bb = b_addr + (t & 1) * BBUF;
#pragma unroll 4
        for (int ks = 0; ks < 16; ++ks) {
            uint32_t a[2][2][4], b[2][2][2];
#pragma unroll
            for (int mt = 0; mt < 2; ++mt)
#pragma unroll
                for (int sp = 0; sp < 2; ++sp)
                    ldsm_x4(a[mt][sp], a_addr + mt * (16 * PITCH) + sp * ASPLIT + ks * 32);
#pragma unroll
            for (int nt = 0; nt < 2; ++nt)
#pragma unroll
                for (int sp = 0; sp < 2; ++sp)
                    ldsm_x2(b[nt][sp], bb + nt * (8 * PITCH) + sp * BSPLIT + ks * 32);
#pragma unroll
            for (int mt = 0; mt < 2; ++mt)
#pragma unroll
                for (int nt = 0; nt < 2; ++nt) {
                    mma16816(acc[mt][nt], a[mt][0], b[nt][0]);   // hi*hi
                    mma16816(acc[mt][nt], a[mt][1], b[nt][0]);   // lo*hi
                    mma16816(acc[mt][nt], a[mt][0], b[nt][1]);   // hi*lo
                }
        }

        // top-2 update. D frag: reg r -> row (lane>>2)+8*(r>>1), col (lane&3)*2+(r&1)
        const float* qp = csq_s + (t & 1) * 64;
#pragma unroll
        for (int mt = 0; mt < 2; ++mt)
#pragma unroll
            for (int nt = 0; nt < 2; ++nt) {
                int cin = ncol0 + nt * 8 + (lane & 3) * 2;
#pragma unroll
                for (int r = 0; r < 4; ++r) {
                    float d = qp[cin + (r & 1)] - acc[mt][nt][r];
                    int code = t * 64 + cin + (r & 1);
                    int s = mt * 2 + (r >> 1);
                    if (d < best1[s]) { best2[s] = best1[s]; id2[s] = id1[s]; best1[s] = d; id1[s] = code; }
                    else if (d < best2[s]) { best2[s] = d; id2[s] = code; }
                }
            }
    }

    // cross-thread reduce: per row, 16 threads x top-2 = 32 candidates.
    __syncthreads();
    float* red_d = (float*)(smem + RED_OFF);          // [64][32]
    int*   red_i = (int*)(smem + RED_OFF + 8192);     // [64][32]
#pragma unroll
    for (int s = 0; s < 4; ++s) {
        int row_l = mrow0 + (s >> 1) * 16 + (s & 1) * 8 + (lane >> 2);
        int e = (warp >> 1) * 8 + (lane & 3) * 2;
        red_d[row_l * 32 + e]     = best1[s];  red_i[row_l * 32 + e]     = id1[s];
        red_d[row_l * 32 + e + 1] = best2[s];  red_i[row_l * 32 + e + 1] = id2[s];
    }
    __syncthreads();
    if (tid < 64) {
        float b1 = CUDART_INF_F, b2 = CUDART_INF_F; int i1 = 0, i2 = 0;
#pragma unroll
        for (int j = 0; j < 32; ++j) {
            float d = red_d[tid * 32 + j]; int ix = red_i[tid * 32 + j];
            if (d < b1 || (d == b1 && ix < i1)) { b2 = b1; i2 = i1; b1 = d; i1 = ix; }
            else if (d < b2 || (d == b2 && ix < i2)) { b2 = d; i2 = ix; }
        }
        g_cand[row0 + tid] = make_int2(i1, i2);
    }
}

// ---------------------------------------------------------------------------
// Kernel 4: exact fp32 rescoring of the top-2 candidates. One warp per row.
// ---------------------------------------------------------------------------
__global__ void __launch_bounds__(256) rescore_kernel(const float* __restrict__ cb,
                                                      float* __restrict__ out) {
    int wid = threadIdx.x >> 5, lane = threadIdx.x & 31;
    int row = blockIdx.x * 8 + wid;
    int2 cand = g_cand[row];
    const float* hr = g_h + (size_t)row * CDIM;
    const float* c1 = cb + (size_t)cand.x * CDIM;
    const float* c2 = cb + (size_t)cand.y * CDIM;
    float d1 = 0.f, d2 = 0.f;
#pragma unroll
    for (int j = 0; j < 8; ++j) {
        float hv = hr[lane + 32 * j];
        d1 = fmaf(hv, c1[lane + 32 * j], d1);
        d2 = fmaf(hv, c2[lane + 32 * j], d2);
    }
#pragma unroll
    for (int o = 16; o; o >>= 1) {
        d1 += __shfl_xor_sync(0xffffffffu, d1, o);
        d2 += __shfl_xor_sync(0xffffffffu, d2, o);
    }
    if (lane == 0) {
        float q1 = g_hcsq[cand.x] - d1;
        float q2 = g_hcsq[cand.y] - d2;
        int bi;
        if (q1 < q2) bi = cand.x;
        else if (q2 < q1) bi = cand.y;
        else bi = min(cand.x, cand.y);
        out[row] = (float)bi;          // float32: harness __output__ dtype
    }
}

// ---------------------------------------------------------------------------
extern "C" void kernel_launch(void* const* d_in, const int* in_sizes, int n_in,
                              void* d_out, int out_size) {
    const float *x = 0, *W = 0, *cbk = 0;
    for (int i = 0; i < n_in; ++i) {
        if      (in_sizes[i] == ROWS_TOTAL * DIM) x   = (const float*)d_in[i];
        else if (in_sizes[i] == CDIM * DIM)       W   = (const float*)d_in[i];
        else if (in_sizes[i] == NCODES * CDIM)    cbk = (const float*)d_in[i];
    }
    float* out = (float*)d_out;
    if (!x || !W || !cbk) return;

    csq_kernel<<<NCODES / 8, 256>>>(cbk);
    cbsplit_kernel<<<NCODES * CDIM / 1024, 256>>>(cbk);
    gemm1_ln_kernel<<<ROWS_TOTAL / 64, 256>>>(x, W);

    cudaFuncSetAttribute(mma_argmin_kernel, cudaFuncAttributeMaxDynamicSharedMemorySize, SM_TOTAL);
    mma_argmin_kernel<<<ROWS_TOTAL / 64, 256, SM_TOTAL>>>();

    rescore_kernel<<<ROWS_TOTAL / 8, 256>>>(cbk, out);
}